// round 7
// baseline (speedup 1.0000x reference)
#include <cuda_runtime.h>
#include <cstdint>
#include <cstddef>

// ============================================================================
// RNNSequence: h_t = tanh(x_t @ W_ih + h_{t-1} @ W_hh + b), out[b,t,:] = h_t
// B=32, T=2048, D_IN=512, D_H=512, fp32.
//
// Phase 1: gemm_xw writes xw = x@W_ih + b into d_out (65536x512, f32x2 FMA).
// Phase 2: rnn_scan: 16 clusters x 8 CTAs x 256 thr, batches {2c,2c+1}.
//          W_hh slice in registers (64 f32x2/thread). Per-step exchange:
//          stage 512B locally, 8x cp.async.bulk (shared::cta ->
//          shared::cluster) with mbarrier complete_tx into each peer's
//          full[nb] barrier. Consumers try_wait parity. NO per-step
//          barrier.cluster, NO fences, NO remote scalar stores.
// ============================================================================

constexpr int SEQ = 2048;
constexpr int DH  = 512;

__device__ __forceinline__ unsigned long long pack2(float lo, float hi) {
    unsigned long long r;
    unsigned l = __float_as_uint(lo), h = __float_as_uint(hi);
    asm("mov.b64 %0, {%1, %2};" : "=l"(r) : "r"(l), "r"(h));
    return r;
}
__device__ __forceinline__ void unpack2(unsigned long long v, float& lo, float& hi) {
    unsigned l, h;
    asm("mov.b64 {%0, %1}, %2;" : "=r"(l), "=r"(h) : "l"(v));
    lo = __uint_as_float(l);
    hi = __uint_as_float(h);
}
__device__ __forceinline__ void fma2(unsigned long long& acc,
                                     unsigned long long a, unsigned long long b) {
    asm("fma.rn.f32x2 %0, %1, %2, %0;" : "+l"(acc) : "l"(a), "l"(b));
}

// ---------------------------------------------------------------------------
// Phase 1: C[M,512] = A[M,512] @ B[512,512] + bias  (128x128x16, f32x2)
// ---------------------------------------------------------------------------
__global__ __launch_bounds__(256, 2) void gemm_xw(const float* __restrict__ A,
                                                  const float* __restrict__ B,
                                                  const float* __restrict__ bias,
                                                  float* __restrict__ C) {
    constexpr int K = 512, N = 512;
    __shared__ __align__(16) float As[16][128];
    __shared__ __align__(16) float Bs[16][128];

    const int tid  = threadIdx.x;
    const int row0 = blockIdx.y * 128;
    const int col0 = blockIdx.x * 128;
    const int ty   = tid >> 4;
    const int tx   = tid & 15;

    unsigned long long acc2[8][4];
#pragma unroll
    for (int i = 0; i < 8; i++)
#pragma unroll
        for (int j = 0; j < 4; j++) acc2[i][j] = 0ULL;

    for (int k0 = 0; k0 < K; k0 += 16) {
#pragma unroll
        for (int i = 0; i < 2; i++) {
            int s  = tid + i * 256;
            int m  = s & 127;
            int kg = (s >> 7) << 2;
            float4 v = *(const float4*)(A + (size_t)(row0 + m) * K + (k0 + kg));
            As[kg + 0][m] = v.x;
            As[kg + 1][m] = v.y;
            As[kg + 2][m] = v.z;
            As[kg + 3][m] = v.w;
        }
#pragma unroll
        for (int i = 0; i < 2; i++) {
            int s  = tid + i * 256;
            int n4 = (s & 31) << 2;
            int kk = s >> 5;
            *(float4*)(&Bs[kk][n4]) =
                *(const float4*)(B + (size_t)(k0 + kk) * N + col0 + n4);
        }
        __syncthreads();

#pragma unroll
        for (int kk = 0; kk < 16; kk++) {
            float a[8];
            *(float4*)(a)     = *(const float4*)(&As[kk][ty * 8]);
            *(float4*)(a + 4) = *(const float4*)(&As[kk][ty * 8 + 4]);
            ulonglong2 b01 = *(const ulonglong2*)(&Bs[kk][tx * 8]);
            ulonglong2 b23 = *(const ulonglong2*)(&Bs[kk][tx * 8 + 4]);
            unsigned long long bb[4] = {b01.x, b01.y, b23.x, b23.y};
#pragma unroll
            for (int i = 0; i < 8; i++) {
                unsigned au = __float_as_uint(a[i]);
                unsigned long long ad;
                asm("mov.b64 %0, {%1, %1};" : "=l"(ad) : "r"(au));
#pragma unroll
                for (int j2 = 0; j2 < 4; j2++) fma2(acc2[i][j2], ad, bb[j2]);
            }
        }
        __syncthreads();
    }

    float bv[8];
    *(float4*)(bv)     = *(const float4*)(bias + col0 + tx * 8);
    *(float4*)(bv + 4) = *(const float4*)(bias + col0 + tx * 8 + 4);

#pragma unroll
    for (int i = 0; i < 8; i++) {
        float o[8];
#pragma unroll
        for (int j2 = 0; j2 < 4; j2++) {
            float lo, hi;
            unpack2(acc2[i][j2], lo, hi);
            o[j2 * 2]     = lo + bv[j2 * 2];
            o[j2 * 2 + 1] = hi + bv[j2 * 2 + 1];
        }
        float* cp = C + (size_t)(row0 + ty * 8 + i) * N + col0 + tx * 8;
        *(float4*)(cp)     = *(float4*)(o);
        *(float4*)(cp + 4) = *(float4*)(o + 4);
    }
}

// ---------------------------------------------------------------------------
// Phase 2: 8-CTA clusters, W in registers, cp.async.bulk + mbarrier pipeline
// ---------------------------------------------------------------------------
__device__ __forceinline__ uint32_t smem_u32(const void* p) {
    return (uint32_t)__cvta_generic_to_shared(p);
}

// Precise tanh robust to --use_fast_math (expm1f is never substituted).
__device__ __forceinline__ float tanh_precise(float x) {
    float ax = fabsf(x);
    float em = expm1f(-2.0f * ax);
    float r  = -em / (2.0f + em);
    return copysignf(r, x);
}

__device__ __forceinline__ void mbar_init(uint32_t addr, uint32_t cnt) {
    asm volatile("mbarrier.init.shared.b64 [%0], %1;" :: "r"(addr), "r"(cnt) : "memory");
}
__device__ __forceinline__ void mbar_arrive_expect_tx(uint32_t addr, uint32_t bytes) {
    asm volatile("mbarrier.arrive.expect_tx.shared.b64 _, [%0], %1;"
                 :: "r"(addr), "r"(bytes) : "memory");
}
__device__ __forceinline__ void mbar_wait(uint32_t addr, uint32_t phase) {
    asm volatile(
        "{\n\t"
        ".reg .pred P;\n\t"
        "WAITLP_%=:\n\t"
        "mbarrier.try_wait.parity.acquire.cta.shared::cta.b64 P, [%0], %1, 0x989680;\n\t"
        "@!P bra WAITLP_%=;\n\t"
        "}"
        :: "r"(addr), "r"(phase) : "memory");
}
// Bulk DSMEM copy: local shared -> peer shared, complete_tx on peer's mbarrier.
__device__ __forceinline__ void bulk_copy_cluster(uint32_t dst, uint32_t src,
                                                  uint32_t bytes, uint32_t rmbar) {
    asm volatile(
        "cp.async.bulk.shared::cluster.shared::cta.mbarrier::complete_tx::bytes "
        "[%0], [%1], %2, [%3];"
        :: "r"(dst), "r"(src), "r"(bytes), "r"(rmbar) : "memory");
}

__global__ __launch_bounds__(256, 1) void rnn_scan(float* __restrict__ out,
                                                   const float* __restrict__ Whh) {
    // h organized by SOURCE rank: [buf][rank][batch][64]; rank block = 512B.
    __shared__ __align__(16) float hbuf[2][8][2][64];
    __shared__ __align__(16) float staged[2][64];     // [batch][j], 512B
    __shared__ __align__(8) unsigned long long mbar[2];  // full0, full1

    const int tid   = threadIdx.x;
    const int r     = blockIdx.x & 7;    // rank in cluster
    const int c     = blockIdx.x >> 3;   // cluster id (0..15)
    const int jbase = r * 64;

    const int j   = tid >> 2;            // 0..63
    const int kq  = tid & 3;             // 0..3
    const int col = jbase + j;
    const int k0  = kq * 128;

    // W_hh slice in registers: w2[i] = (Whh[k0+2i][col], Whh[k0+2i+1][col])
    unsigned long long w2[64];
#pragma unroll
    for (int i = 0; i < 64; i++) {
        float lo = Whh[(size_t)(k0 + 2 * i)     * 512 + col];
        float hi = Whh[(size_t)(k0 + 2 * i + 1) * 512 + col];
        w2[i] = pack2(lo, hi);
    }

    for (int idx = tid; idx < 2 * 8 * 2 * 64; idx += 256)
        ((float*)hbuf)[idx] = 0.0f;

    const uint32_t mbB = smem_u32(mbar);
    if (tid == 0) {
        mbar_init(mbB + 0, 1);   // full0: one local arrive.expect_tx per phase
        mbar_init(mbB + 8, 1);   // full1
        asm volatile("fence.mbarrier_init.release.cluster;" ::: "memory");
    }
    __syncthreads();
    // hbuf zeroed + barriers live in ALL CTAs before any bulk lands.
    asm volatile("barrier.cluster.arrive.aligned;" ::: "memory");
    asm volatile("barrier.cluster.wait.aligned;"   ::: "memory");

    if (tid == 0) {
        mbar_arrive_expect_tx(mbB + 0, 4096);   // arm full0 phase 0
        mbar_arrive_expect_tx(mbB + 8, 4096);   // arm full1 phase 0
    }

    // Peer addresses
    const uint32_t hbB = smem_u32(hbuf);
    const uint32_t stB = smem_u32(staged);
    uint32_t peer_h = 0, peer_m = 0;
    if (tid < 8) {
        asm("mapa.shared::cluster.u32 %0, %1, %2;" : "=r"(peer_h) : "r"(hbB), "r"(tid));
        asm("mapa.shared::cluster.u32 %0, %1, %2;" : "=r"(peer_m) : "r"(mbB), "r"(tid));
    }

    // writer role: kq==0 -> batch 2c, kq==1 -> batch 2c+1
    const int batch = (kq < 2) ? kq : 0;
    const int gj    = jbase + j;
    float* outp = out + ((size_t)(c * 2 + batch) * SEQ) * DH + gj;

    // xw prefetch pipeline (one step ahead)
    float xw_next = 0.0f;
    if (kq < 2) xw_next = __ldg(outp);

    int ph0 = 0, ph1 = 0;

    for (int t = 0; t < SEQ; ++t) {
        const int cur = t & 1;
        const int nb  = cur ^ 1;

        float xwv = xw_next;
        if (kq < 2 && t + 1 < SEQ) xw_next = __ldg(outp + (size_t)(t + 1) * DH);

        if (t > 0) {
            if (cur) { mbar_wait(mbB + 8, ph1); ph1 ^= 1; }
            else     { mbar_wait(mbB + 0, ph0); ph0 ^= 1; }
            // Re-arm this barrier for its next use (step t+2). Our own step-t
            // bulk (issued after the syncthreads below) causally precedes any
            // peer bytes for that phase, so the arm always lands first.
            if (tid == 0)
                mbar_arrive_expect_tx(mbB + (cur ? 8 : 0), 4096);
        }

        // k-chunk [128kq,128kq+128) = rank 2kq cols ++ rank 2kq+1 cols
        const float* basef = &hbuf[cur][0][0][0];
        const ulonglong2* pa0 = (const ulonglong2*)(basef + (2 * kq) * 128);
        const ulonglong2* pb0 = (const ulonglong2*)(basef + (2 * kq) * 128 + 64);
        const ulonglong2* pa1 = (const ulonglong2*)(basef + (2 * kq + 1) * 128);
        const ulonglong2* pb1 = (const ulonglong2*)(basef + (2 * kq + 1) * 128 + 64);

        unsigned long long aA0 = 0ULL, aA1 = 0ULL, aB0 = 0ULL, aB1 = 0ULL;
#pragma unroll
        for (int i = 0; i < 16; i++) {
            ulonglong2 xa = pa0[i];
            ulonglong2 xb = pa1[i];
            ulonglong2 ya = pb0[i];
            ulonglong2 yb = pb1[i];
            fma2(aA0, w2[2 * i],          xa.x);
            fma2(aA0, w2[2 * i + 1],      xa.y);
            fma2(aA1, w2[32 + 2 * i],     xb.x);
            fma2(aA1, w2[32 + 2 * i + 1], xb.y);
            fma2(aB0, w2[2 * i],          ya.x);
            fma2(aB0, w2[2 * i + 1],      ya.y);
            fma2(aB1, w2[32 + 2 * i],     yb.x);
            fma2(aB1, w2[32 + 2 * i + 1], yb.y);
        }
        float a0l, a0h, a1l, a1h, b0l, b0h, b1l, b1h;
        unpack2(aA0, a0l, a0h);
        unpack2(aA1, a1l, a1h);
        unpack2(aB0, b0l, b0h);
        unpack2(aB1, b1l, b1h);
        float pA = (a0l + a0h) + (a1l + a1h);
        float pB = (b0l + b0h) + (b1l + b1h);
        pA += __shfl_xor_sync(0xffffffffu, pA, 1);
        pB += __shfl_xor_sync(0xffffffffu, pB, 1);
        pA += __shfl_xor_sync(0xffffffffu, pA, 2);
        pB += __shfl_xor_sync(0xffffffffu, pB, 2);

        if (kq < 2) {
            float s  = (kq == 0 ? pA : pB) + xwv;
            float hn = tanh_precise(s);
            outp[(size_t)t * DH] = hn;
            staged[kq][j] = hn;          // [batch][j], contiguous 512B
        }

        if (t < SEQ - 1) {
            __syncthreads();             // staged complete; hbuf[cur] reads done
            if (tid < 8) {
                // Make generic-proxy staged[] writes visible to bulk engine.
                asm volatile("fence.proxy.async.shared::cta;" ::: "memory");
                uint32_t dst = peer_h + (uint32_t)(nb * 8 + r) * 512u;
                uint32_t mb  = peer_m + (uint32_t)nb * 8u;
                bulk_copy_cluster(dst, stB, 512u, mb);
            }
        }
    }

    // Keep SMEM alive until the whole cluster is done consuming.
    asm volatile("barrier.cluster.arrive.aligned;" ::: "memory");
    asm volatile("barrier.cluster.wait.aligned;"   ::: "memory");
}

// ---------------------------------------------------------------------------
// Launch
// ---------------------------------------------------------------------------
extern "C" void kernel_launch(void* const* d_in, const int* in_sizes, int n_in,
                              void* d_out, int out_size) {
    const float* x    = (const float*)d_in[0];  // [32,2048,512]
    const float* W_ih = (const float*)d_in[1];  // [512,512]
    const float* W_hh = (const float*)d_in[2];  // [512,512]
    const float* bias = (const float*)d_in[3];  // [512]
    float* out = (float*)d_out;                 // [32,2048,512]

    dim3 ggrid(512 / 128, (32 * SEQ) / 128);    // (4, 512)
    gemm_xw<<<ggrid, 256>>>(x, W_ih, bias, out);

    cudaLaunchConfig_t cfg = {};
    cfg.gridDim          = dim3(128, 1, 1);     // 16 clusters x 8 CTAs
    cfg.blockDim         = dim3(256, 1, 1);
    cfg.dynamicSmemBytes = 0;
    cfg.stream           = 0;

    cudaLaunchAttribute attrs[1];
    attrs[0].id = cudaLaunchAttributeClusterDimension;
    attrs[0].val.clusterDim.x = 8;
    attrs[0].val.clusterDim.y = 1;
    attrs[0].val.clusterDim.z = 1;
    cfg.attrs    = attrs;
    cfg.numAttrs = 1;

    cudaLaunchKernelEx(&cfg, rnn_scan, out, W_hh);
}

// round 8
// speedup vs baseline: 3.4008x; 3.4008x over previous
#include <cuda_runtime.h>
#include <cstdint>
#include <cstddef>

// ============================================================================
// RNNSequence: h_t = tanh(x_t @ W_ih + h_{t-1} @ W_hh + b), out[b,t,:] = h_t
// B=32, T=2048, D_IN=512, D_H=512, fp32.
//
// Phase 1: gemm_xw writes xw = x@W_ih + b into d_out (65536x512, f32x2 FMA).
// Phase 2: rnn_scan: NO clusters. 128 CTAs = 16 groups x 8 ranks, group g
//          owns batches {2g,2g+1}; rank r owns output cols [64r,64r+64).
//          W_hh slice in registers. h exchanged through L2:
//            produce: st.global.cg h slice -> syncthreads -> st.release.gpu flag
//            consume: ld.acquire.gpu poll 8 flags -> syncthreads -> 4KB __ldcg
//                     stage into smem -> compute.
//          Flags are MONOTONIC across launches (graph-replay safe); t=0 uses
//          h=0 directly so g_h needs no initialization.
// ============================================================================

constexpr int SEQ = 2048;
constexpr int DH  = 512;

// L2-resident exchange state. g_h never needs init (iteration 0 reads nothing;
// each launch's iteration t>=1 reads only data published earlier in the SAME
// launch). g_flag starts 0 (static init) and only grows.
__device__ float    g_h[2][16][8][2][64];   // [buf][group][rank][batch][j]
__device__ unsigned g_flag[16][32];          // [group][rank], 128B padded rows

__device__ __forceinline__ unsigned long long pack2(float lo, float hi) {
    unsigned long long r;
    unsigned l = __float_as_uint(lo), h = __float_as_uint(hi);
    asm("mov.b64 %0, {%1, %2};" : "=l"(r) : "r"(l), "r"(h));
    return r;
}
__device__ __forceinline__ void unpack2(unsigned long long v, float& lo, float& hi) {
    unsigned l, h;
    asm("mov.b64 {%0, %1}, %2;" : "=r"(l), "=r"(h) : "l"(v));
    lo = __uint_as_float(l);
    hi = __uint_as_float(h);
}
__device__ __forceinline__ void fma2(unsigned long long& acc,
                                     unsigned long long a, unsigned long long b) {
    asm("fma.rn.f32x2 %0, %1, %2, %0;" : "+l"(acc) : "l"(a), "l"(b));
}

// ---------------------------------------------------------------------------
// Phase 1: C[M,512] = A[M,512] @ B[512,512] + bias  (128x128x16, f32x2)
// ---------------------------------------------------------------------------
__global__ __launch_bounds__(256, 2) void gemm_xw(const float* __restrict__ A,
                                                  const float* __restrict__ B,
                                                  const float* __restrict__ bias,
                                                  float* __restrict__ C) {
    constexpr int K = 512, N = 512;
    __shared__ __align__(16) float As[16][128];
    __shared__ __align__(16) float Bs[16][128];

    const int tid  = threadIdx.x;
    const int row0 = blockIdx.y * 128;
    const int col0 = blockIdx.x * 128;
    const int ty   = tid >> 4;
    const int tx   = tid & 15;

    unsigned long long acc2[8][4];
#pragma unroll
    for (int i = 0; i < 8; i++)
#pragma unroll
        for (int j = 0; j < 4; j++) acc2[i][j] = 0ULL;

    for (int k0 = 0; k0 < K; k0 += 16) {
#pragma unroll
        for (int i = 0; i < 2; i++) {
            int s  = tid + i * 256;
            int m  = s & 127;
            int kg = (s >> 7) << 2;
            float4 v = *(const float4*)(A + (size_t)(row0 + m) * K + (k0 + kg));
            As[kg + 0][m] = v.x;
            As[kg + 1][m] = v.y;
            As[kg + 2][m] = v.z;
            As[kg + 3][m] = v.w;
        }
#pragma unroll
        for (int i = 0; i < 2; i++) {
            int s  = tid + i * 256;
            int n4 = (s & 31) << 2;
            int kk = s >> 5;
            *(float4*)(&Bs[kk][n4]) =
                *(const float4*)(B + (size_t)(k0 + kk) * N + col0 + n4);
        }
        __syncthreads();

#pragma unroll
        for (int kk = 0; kk < 16; kk++) {
            float a[8];
            *(float4*)(a)     = *(const float4*)(&As[kk][ty * 8]);
            *(float4*)(a + 4) = *(const float4*)(&As[kk][ty * 8 + 4]);
            ulonglong2 b01 = *(const ulonglong2*)(&Bs[kk][tx * 8]);
            ulonglong2 b23 = *(const ulonglong2*)(&Bs[kk][tx * 8 + 4]);
            unsigned long long bb[4] = {b01.x, b01.y, b23.x, b23.y};
#pragma unroll
            for (int i = 0; i < 8; i++) {
                unsigned au = __float_as_uint(a[i]);
                unsigned long long ad;
                asm("mov.b64 %0, {%1, %1};" : "=l"(ad) : "r"(au));
#pragma unroll
                for (int j2 = 0; j2 < 4; j2++) fma2(acc2[i][j2], ad, bb[j2]);
            }
        }
        __syncthreads();
    }

    float bv[8];
    *(float4*)(bv)     = *(const float4*)(bias + col0 + tx * 8);
    *(float4*)(bv + 4) = *(const float4*)(bias + col0 + tx * 8 + 4);

#pragma unroll
    for (int i = 0; i < 8; i++) {
        float o[8];
#pragma unroll
        for (int j2 = 0; j2 < 4; j2++) {
            float lo, hi;
            unpack2(acc2[i][j2], lo, hi);
            o[j2 * 2]     = lo + bv[j2 * 2];
            o[j2 * 2 + 1] = hi + bv[j2 * 2 + 1];
        }
        float* cp = C + (size_t)(row0 + ty * 8 + i) * N + col0 + tx * 8;
        *(float4*)(cp)     = *(float4*)(o);
        *(float4*)(cp + 4) = *(float4*)(o + 4);
    }
}

// ---------------------------------------------------------------------------
// Phase 2: L2 flag-pipelined scan
// ---------------------------------------------------------------------------
// smem h layout: [rank][batch][64] with rank stride 132 floats (528B).
// kq lanes read ranks {2kq, 2kq+1}: bank phase = (264*kq)%32*4B -> 0,8,16,24:
// conflict-free; 8 j-lanes broadcast the same address.
constexpr int RSTRIDE = 132;

__device__ __forceinline__ float tanh_precise(float x) {
    float ax = fabsf(x);
    float em = expm1f(-2.0f * ax);
    float r  = -em / (2.0f + em);
    return copysignf(r, x);
}

__device__ __forceinline__ unsigned ld_acquire_gpu(const unsigned* p) {
    unsigned v;
    asm volatile("ld.acquire.gpu.u32 %0, [%1];" : "=r"(v) : "l"(p) : "memory");
    return v;
}
__device__ __forceinline__ void st_release_gpu(unsigned* p, unsigned v) {
    asm volatile("st.release.gpu.u32 [%0], %1;" :: "l"(p), "r"(v) : "memory");
}

__global__ __launch_bounds__(256, 1) void rnn_scan(float* __restrict__ out,
                                                   const float* __restrict__ Whh) {
    __shared__ __align__(16) float hs[8 * RSTRIDE];

    const int tid = threadIdx.x;
    const int r   = blockIdx.x & 7;     // rank in group
    const int g   = blockIdx.x >> 3;    // group id (0..15)

    const int j   = tid >> 2;           // 0..63
    const int kq  = tid & 3;            // 0..3
    const int col = r * 64 + j;
    const int k0  = kq * 128;

    // W_hh slice in registers: w2[i] = (Whh[k0+2i][col], Whh[k0+2i+1][col])
    unsigned long long w2[64];
#pragma unroll
    for (int i = 0; i < 64; i++) {
        float lo = Whh[(size_t)(k0 + 2 * i)     * 512 + col];
        float hi = Whh[(size_t)(k0 + 2 * i + 1) * 512 + col];
        w2[i] = pack2(lo, hi);
    }

    // Monotonic flag base: quiescent at launch; only this CTA writes its flag.
    const unsigned base = *(volatile unsigned*)&g_flag[g][r];
    unsigned* const flags = &g_flag[g][0];

    // writer role: kq==0 -> batch 2g, kq==1 -> batch 2g+1
    const int batch = (kq < 2) ? kq : 0;
    const int gj    = col;
    float* outp = out + ((size_t)(g * 2 + batch) * SEQ) * DH + gj;

    // stage/publish pointers
    const float4* const stage_src[2] = {
        (const float4*)&g_h[0][g][0][0][0],
        (const float4*)&g_h[1][g][0][0][0]
    };
    float* const hw[2] = { &g_h[0][g][r][0][0], &g_h[1][g][r][0][0] };

    // stage role: warp w stages rank w's 512B block
    const int srank = tid >> 5;
    const int sw    = tid & 31;
    float* const sdst = hs + srank * RSTRIDE + sw * 4;

    // xw prefetch pipeline (one step ahead)
    float xw_next = 0.0f;
    if (kq < 2) xw_next = __ldg(outp);

    for (int t = 0; t < SEQ; ++t) {
        const int cur = t & 1;
        const int nb  = cur ^ 1;

        float xwv = xw_next;
        if (kq < 2 && t + 1 < SEQ) xw_next = __ldg(outp + (size_t)(t + 1) * DH);

        float pA = 0.0f, pB = 0.0f;
        if (t > 0) {
            // Wait: all 8 ranks published o_{t-1} (flag >= base+t).
            if (tid < 8) {
                const unsigned target = base + (unsigned)t;
                while ((int)(ld_acquire_gpu(flags + tid) - target) < 0) {}
            }
            __syncthreads();
            // Stage 4KB h (o_{t-1}) from L2 into smem, padded layout.
            float4 v = __ldcg(stage_src[cur] + tid);
            *(float4*)sdst = v;
            __syncthreads();

            // Compute: thread (j,kq) covers k in [128kq,128kq+128) for 2 batches.
            const ulonglong2* pa0 = (const ulonglong2*)(hs + (2 * kq)     * RSTRIDE);
            const ulonglong2* pa1 = (const ulonglong2*)(hs + (2 * kq + 1) * RSTRIDE);
            const ulonglong2* pb0 = (const ulonglong2*)(hs + (2 * kq)     * RSTRIDE + 64);
            const ulonglong2* pb1 = (const ulonglong2*)(hs + (2 * kq + 1) * RSTRIDE + 64);

            unsigned long long aA0 = 0ULL, aA1 = 0ULL, aB0 = 0ULL, aB1 = 0ULL;
#pragma unroll
            for (int i = 0; i < 16; i++) {
                ulonglong2 xa = pa0[i];
                ulonglong2 xb = pa1[i];
                ulonglong2 ya = pb0[i];
                ulonglong2 yb = pb1[i];
                fma2(aA0, w2[2 * i],          xa.x);
                fma2(aA0, w2[2 * i + 1],      xa.y);
                fma2(aA1, w2[32 + 2 * i],     xb.x);
                fma2(aA1, w2[32 + 2 * i + 1], xb.y);
                fma2(aB0, w2[2 * i],          ya.x);
                fma2(aB0, w2[2 * i + 1],      ya.y);
                fma2(aB1, w2[32 + 2 * i],     yb.x);
                fma2(aB1, w2[32 + 2 * i + 1], yb.y);
            }
            float a0l, a0h, a1l, a1h, b0l, b0h, b1l, b1h;
            unpack2(aA0, a0l, a0h);
            unpack2(aA1, a1l, a1h);
            unpack2(aB0, b0l, b0h);
            unpack2(aB1, b1l, b1h);
            pA = (a0l + a0h) + (a1l + a1h);
            pB = (b0l + b0h) + (b1l + b1h);
            pA += __shfl_xor_sync(0xffffffffu, pA, 1);
            pB += __shfl_xor_sync(0xffffffffu, pB, 1);
            pA += __shfl_xor_sync(0xffffffffu, pA, 2);
            pB += __shfl_xor_sync(0xffffffffu, pB, 2);
        }

        if (kq < 2) {
            float s  = (kq == 0 ? pA : pB) + xwv;   // t==0: pA=pB=0
            float hn = tanh_precise(s);
            outp[(size_t)t * DH] = hn;
            if (t < SEQ - 1)
                __stcg(hw[nb] + kq * 64 + j, hn);   // publish o_t slice
        }

        if (t < SEQ - 1) {
            // All data stores done CTA-wide, then release the flag.
            // Overwrite safety: we write buf[nb]; any peer last read buf[nb]
            // at its iteration t-1, which completed before it set flag>=base+t
            // (we observed that flag at the top of this iteration).
            __syncthreads();
            if (tid == 0)
                st_release_gpu(flags + r, base + (unsigned)(t + 1));
        }
    }
}

// ---------------------------------------------------------------------------
// Launch
// ---------------------------------------------------------------------------
extern "C" void kernel_launch(void* const* d_in, const int* in_sizes, int n_in,
                              void* d_out, int out_size) {
    const float* x    = (const float*)d_in[0];  // [32,2048,512]
    const float* W_ih = (const float*)d_in[1];  // [512,512]
    const float* W_hh = (const float*)d_in[2];  // [512,512]
    const float* bias = (const float*)d_in[3];  // [512]
    float* out = (float*)d_out;                 // [32,2048,512]

    dim3 ggrid(512 / 128, (32 * SEQ) / 128);    // (4, 512)
    gemm_xw<<<ggrid, 256>>>(x, W_ih, bias, out);

    // 128 plain CTAs (single wave on 148 SMs — required for spin safety).
    rnn_scan<<<128, 256>>>(out, W_hh);
}